// round 9
// baseline (speedup 1.0000x reference)
#include <cuda_runtime.h>

#define NG 1024
#define R0 8192
#define C0 4096
#define R1 4096
#define C1 2048
#define RM 512

#define GPB 8                   // groups per obsA block
#define A_BLOCKS 512            // (1024/8 group-sets) x (4096/1024 col tiles)
#define P1_BLOCKS 512           // theta1 rows / 8 rows-per-block
#define C_BLOCKS 16
#define B_SPLIT 2               // blocks per mapping row (two-stage dot)
#define B_BLOCKS (RM * B_SPLIT) // 1024
#define LCAP 256                // per-group row list capacity (mean cnt = 8)
#define FCAP 1024               // flat list capacity (actual total ~64)

// Scratch (device globals — zero at process start; restored to zero at the
// end of every call, so no zero-prologue kernel).
__device__ float  g_p2[C0];
__device__ float  g_p1[R1];
__device__ float  g_m1[RM];     // two-stage obs-B partial dots
__device__ int    g_bcnt[RM];   // per-row arrival counters
__device__ double g_loss[3];
__device__ int    g_done;

__device__ __forceinline__ float block_reduce256(float v, float* sh) {
    int t = threadIdx.x;
    #pragma unroll
    for (int o = 16; o; o >>= 1) v += __shfl_down_sync(0xffffffffu, v, o);
    if ((t & 31) == 0) sh[t >> 5] = v;
    __syncthreads();
    if (t < 8) {
        v = sh[t];
        #pragma unroll
        for (int o = 4; o; o >>= 1) v += __shfl_down_sync(0x000000ffu, v, o);
    }
    return v; // valid in thread 0
}

// ---------------------------------------------------------------------------
// Main fused kernel. A-blocks and P1-blocks interleaved by bid parity.
//  A-block: 8 groups x 1024 columns. Vectorized private scan of the
//    L2-resident idx vector -> flat ordered row list -> streamed in 8-row
//    chunks with all 8 float4 loads in named registers (uniform MLP=8).
//  P1-block: 8 rows of theta1, rowsum of exp, one warp per row.
// ---------------------------------------------------------------------------
__global__ __launch_bounds__(256) void k_main(const float* __restrict__ theta0,
                                              const float* __restrict__ obs0,
                                              const float* __restrict__ theta1,
                                              const unsigned int* __restrict__ idx_raw) {
    int bx = blockIdx.x;
    if ((bx & 1) == 0) {
        // ----------------- obs-A -----------------
        int ab = bx >> 1;               // 0..511
        __shared__ int   scnt[GPB];
        __shared__ short slist[GPB * LCAP];
        __shared__ short sflat[FCAP];
        __shared__ float sh[8];
        int t = threadIdx.x;
        int gset = ab >> 2;             // 0..127
        int tile = ab & 3;              // 0..3
        int g0 = gset * GPB;
        int c = tile * 1024 + t * 4;

        if (t < GPB) scnt[t] = 0;
        __syncthreads();

        // int64 vs int32 width detection: for int64 values < 1024 every odd
        // 32-bit word is zero; for int32 odd words are random group ids.
        unsigned int hi = 0;
        #pragma unroll
        for (int s = 0; s < 4; s++) hi |= idx_raw[2 * (t + 256 * s) + 1];
        int is32 = __syncthreads_or(hi != 0u);

        // Vectorized scan of idx, collecting rows in our 8 groups.
        if (is32) {
            const int4* p = (const int4*)idx_raw;
            #pragma unroll
            for (int it = 0; it < 8; it++) {
                int i4 = t + it * 256;          // 2048 int4 total
                int4 v = p[i4];
                int ib = i4 * 4;
                int g;
                g = v.x - g0; if ((unsigned)g < GPB) { int s = atomicAdd(&scnt[g], 1); if (s < LCAP) slist[g * LCAP + s] = (short)(ib + 0); }
                g = v.y - g0; if ((unsigned)g < GPB) { int s = atomicAdd(&scnt[g], 1); if (s < LCAP) slist[g * LCAP + s] = (short)(ib + 1); }
                g = v.z - g0; if ((unsigned)g < GPB) { int s = atomicAdd(&scnt[g], 1); if (s < LCAP) slist[g * LCAP + s] = (short)(ib + 2); }
                g = v.w - g0; if ((unsigned)g < GPB) { int s = atomicAdd(&scnt[g], 1); if (s < LCAP) slist[g * LCAP + s] = (short)(ib + 3); }
            }
        } else {
            const longlong2* p = (const longlong2*)idx_raw;
            #pragma unroll
            for (int it = 0; it < 16; it++) {
                int i2 = t + it * 256;          // 4096 longlong2 total
                longlong2 v = p[i2];
                int ib = i2 * 2;
                int g;
                g = (int)v.x - g0; if ((unsigned)g < GPB) { int s = atomicAdd(&scnt[g], 1); if (s < LCAP) slist[g * LCAP + s] = (short)(ib + 0); }
                g = (int)v.y - g0; if ((unsigned)g < GPB) { int s = atomicAdd(&scnt[g], 1); if (s < LCAP) slist[g * LCAP + s] = (short)(ib + 1); }
            }
        }
        __syncthreads();

        // block-uniform prefix over 8 group counts
        int soff[GPB + 1];
        {
            int acc = 0;
            #pragma unroll
            for (int g = 0; g < GPB; g++) {
                soff[g] = acc;
                int cg = scnt[g];
                if (cg > LCAP) cg = LCAP;
                acc += cg;
                if (acc > FCAP) acc = FCAP;
            }
            soff[GPB] = acc;
        }
        // compact into flat ordered list
        #pragma unroll
        for (int g = 0; g < GPB; g++) {
            int cg = soff[g + 1] - soff[g];
            for (int s = t; s < cg; s += 256)
                sflat[soff[g] + s] = slist[g * LCAP + s];
        }
        __syncthreads();

        int total = soff[GPB];
        int gg = 0;
        int bnd = soff[1];
        float ax = 0.f, ay = 0.f, az = 0.f, aw = 0.f;   // current group sum
        float px = 0.f, py = 0.f, pz = 0.f, pw = 0.f;   // p2 partial (8 groups)
        float lsum = 0.f;                                // loss_a partial

#define FLUSH_GROUP() do {                                                   \
            float4 o_ = *(const float4*)(obs0 + (size_t)(g0 + gg) * C0 + c); \
            float dx_ = o_.x - ax, dy_ = o_.y - ay;                          \
            float dz_ = o_.z - az, dw_ = o_.w - aw;                          \
            lsum += dx_ * dx_ + dy_ * dy_ + dz_ * dz_ + dw_ * dw_;           \
            px += ax; py += ay; pz += az; pw += aw;                          \
            ax = ay = az = aw = 0.f;                                         \
        } while (0)

#define LOADV(VN, K) float4 VN = make_float4(0.f, 0.f, 0.f, 0.f);            \
        if (base + (K) < total) {                                            \
            int r_ = (unsigned short)sflat[base + (K)];                      \
            VN = *(const float4*)(theta0 + (size_t)r_ * C0 + c);             \
        }
#define ACCV(VN, K)                                                          \
        if (base + (K) < total) {                                            \
            int idx_ = base + (K);                                           \
            while (idx_ == bnd) { FLUSH_GROUP(); gg++; bnd = soff[gg + 1]; } \
            ax += __expf(VN.x); ay += __expf(VN.y);                          \
            az += __expf(VN.z); aw += __expf(VN.w);                          \
        }

        for (int base = 0; base < total; base += 8) {
            LOADV(v0, 0) LOADV(v1, 1) LOADV(v2, 2) LOADV(v3, 3)
            LOADV(v4, 4) LOADV(v5, 5) LOADV(v6, 6) LOADV(v7, 7)
            ACCV(v0, 0) ACCV(v1, 1) ACCV(v2, 2) ACCV(v3, 3)
            ACCV(v4, 4) ACCV(v5, 5) ACCV(v6, 6) ACCV(v7, 7)
        }
        while (gg < GPB) { FLUSH_GROUP(); gg++; }
#undef LOADV
#undef ACCV
#undef FLUSH_GROUP

        atomicAdd(&g_p2[c + 0], px);
        atomicAdd(&g_p2[c + 1], py);
        atomicAdd(&g_p2[c + 2], pz);
        atomicAdd(&g_p2[c + 3], pw);

        float v = block_reduce256(lsum, sh);
        if (t == 0) atomicAdd(&g_loss[0], (double)v);
    } else {
        // ----------------- p1 rowsum-of-exp: one warp per theta1 row -------
        int gid = (bx >> 1) * 256 + threadIdx.x;
        int w = gid >> 5, lane = gid & 31;
        const float4* row = (const float4*)(theta1 + (size_t)w * C1);
        float s = 0.f;
        #pragma unroll 4
        for (int j = lane; j < C1 / 4; j += 32) {
            float4 v = row[j];
            s += __expf(v.x) + __expf(v.y) + __expf(v.z) + __expf(v.w);
        }
        #pragma unroll
        for (int o = 16; o; o >>= 1) s += __shfl_down_sync(0xffffffffu, s, o);
        if (lane == 0) g_p1[w] = s;
    }
}

// ---------------------------------------------------------------------------
// Epilogue (1040 blocks).
//  blocks [0, C_BLOCKS): obs-C + restore g_p2.
//  blocks [C_BLOCKS, +B_BLOCKS): obs-B two-stage — 2 blocks per mapping row,
//    each reduces a 2048-col partial dot into g_m1[w]; the second arriver
//    (per-row counter) computes the squared error and restores g_m1/g_bcnt.
//    Two-addend float atomicAdd is exactly commutative -> deterministic.
//  Last finisher writes the output and restores the loss accumulators.
// ---------------------------------------------------------------------------
__global__ __launch_bounds__(256) void k_post(const float* __restrict__ obs2,
                                              const float* __restrict__ mapping1,
                                              const float* __restrict__ obs1,
                                              float* __restrict__ out) {
    __shared__ float sh[8];
    int bx = blockIdx.x;
    int t = threadIdx.x;
    if (bx < C_BLOCKS) {
        int c = bx * 256 + t;
        float d = obs2[c] - g_p2[c];
        g_p2[c] = 0.f;                      // restore for next call
        float v = block_reduce256(d * d, sh);
        if (t == 0) atomicAdd(&g_loss[2], (double)v);
    } else {
        int id = bx - C_BLOCKS;
        int w = id >> 1;                    // mapping row
        int half = id & 1;                  // column half
        const float4* m = (const float4*)(mapping1 + (size_t)w * C0);
        const float4* p = (const float4*)g_p1;
        float s = 0.f;
        #pragma unroll
        for (int j = 0; j < 2; j++) {       // 2048 cols = 512 float4
            int k = half * 512 + t + j * 256;
            float4 a = m[k];
            float4 q = p[k];
            s += a.x * q.x + a.y * q.y + a.z * q.z + a.w * q.w;
        }
        float r = block_reduce256(s, sh);
        if (t == 0) {
            atomicAdd(&g_m1[w], r);
            __threadfence();
            int a = atomicAdd(&g_bcnt[w], 1);
            if (a == B_SPLIT - 1) {         // last arriver for this row
                __threadfence();
                float mres = *(volatile float*)&g_m1[w];
                double d = (double)obs1[w] - (double)mres;
                atomicAdd(&g_loss[1], d * d);
                g_m1[w] = 0.f;              // restore for next call
                g_bcnt[w] = 0;
            }
        }
    }
    __syncthreads();
    __threadfence();
    if (t == 0) {
        int done = atomicAdd(&g_done, 1);
        if (done == (int)gridDim.x - 1) {
            __threadfence();
            double la = *(volatile double*)&g_loss[0];
            double lb = *(volatile double*)&g_loss[1];
            double lc = *(volatile double*)&g_loss[2];
            la /= (double)((size_t)NG * (size_t)C0);
            lb /= (double)RM;
            lc = 0.5 * lc / (double)C0;
            out[0] = (float)((la + lb + lc) / 3.0);
            g_loss[0] = 0.0; g_loss[1] = 0.0; g_loss[2] = 0.0;
            g_done = 0;
        }
    }
}

extern "C" void kernel_launch(void* const* d_in, const int* in_sizes, int n_in,
                              void* d_out, int out_size) {
    const float* theta0   = (const float*)d_in[0];
    const float* theta1   = (const float*)d_in[1];
    const float* obs0     = (const float*)d_in[2];
    const float* obs1     = (const float*)d_in[3];
    const float* obs2     = (const float*)d_in[4];
    const void*  idx0     = d_in[5];
    const float* mapping1 = (const float*)d_in[6];
    float* out = (float*)d_out;

    k_main<<<A_BLOCKS + P1_BLOCKS, 256>>>(theta0, obs0, theta1,
                                          (const unsigned int*)idx0);
    k_post<<<C_BLOCKS + B_BLOCKS, 256>>>(obs2, mapping1, obs1, out);
}

// round 10
// speedup vs baseline: 1.0599x; 1.0599x over previous
#include <cuda_runtime.h>

#define NG 1024
#define R0 8192
#define C0 4096
#define R1 4096
#define C1 2048
#define RM 512

#define GPB 8                   // groups per obsA block
#define A_BLOCKS 512            // (1024/8 group-sets) x (4096/1024 col tiles)
#define P1_BLOCKS 512           // theta1 rows / 8 rows-per-block
#define C_BLOCKS 16
#define B_BLOCKS RM             // one block per mapping row (R6 config: best measured)
#define LCAP 256                // per-group row list capacity (mean cnt = 8)
#define FCAP 1024               // flat list capacity (actual total ~64)

// Scratch (device globals — zero at process start; accumulators restored to
// zero at the end of every call, so no zero-prologue kernel).
__device__ float  g_p2[C0];
__device__ float  g_p1[R1];
__device__ double g_loss[3];
__device__ int    g_done;

__device__ __forceinline__ float block_reduce256(float v, float* sh) {
    int t = threadIdx.x;
    #pragma unroll
    for (int o = 16; o; o >>= 1) v += __shfl_down_sync(0xffffffffu, v, o);
    if ((t & 31) == 0) sh[t >> 5] = v;
    __syncthreads();
    if (t < 8) {
        v = sh[t];
        #pragma unroll
        for (int o = 4; o; o >>= 1) v += __shfl_down_sync(0x000000ffu, v, o);
    }
    return v; // valid in thread 0
}

// ---------------------------------------------------------------------------
// Main fused kernel (R8 configuration — best measured: ~37 us).
// A-blocks and P1-blocks interleaved by bid parity.
//  A-block: 8 groups x 1024 columns. Builds its own row lists from the
//    L2-resident idx vector, compacts them into one flat ordered list, then
//    streams it in 8-row chunks with all 8 loads in flight (uniform MLP=8).
//  P1-block: 8 rows of theta1, rowsum of exp, one warp per row.
// ---------------------------------------------------------------------------
__global__ __launch_bounds__(256) void k_main(const float* __restrict__ theta0,
                                              const float* __restrict__ obs0,
                                              const float* __restrict__ theta1,
                                              const unsigned int* __restrict__ idx_raw) {
    int bx = blockIdx.x;
    if ((bx & 1) == 0) {
        // ----------------- obs-A -----------------
        int ab = bx >> 1;               // 0..511
        __shared__ int   scnt[GPB];
        __shared__ short slist[GPB * LCAP];
        __shared__ short sflat[FCAP];
        __shared__ float sh[8];
        int t = threadIdx.x;
        int gset = ab >> 2;             // 0..127
        int tile = ab & 3;              // 0..3
        int g0 = gset * GPB;
        int c = tile * 1024 + t * 4;

        if (t < GPB) scnt[t] = 0;
        __syncthreads();

        // int64 vs int32 width detection: for int64 values < 1024 every odd
        // 32-bit word is zero; for int32 odd words are random group ids.
        unsigned int hi = 0;
        #pragma unroll
        for (int s = 0; s < 4; s++) hi |= idx_raw[2 * (t + 256 * s) + 1];
        int is32 = __syncthreads_or(hi != 0u);

        // Scan idx, collect rows belonging to our 8 groups.
        if (is32) {
            const int* p = (const int*)idx_raw;
            #pragma unroll 4
            for (int i = t; i < R0; i += 256) {
                int g = p[i] - g0;
                if ((unsigned)g < GPB) {
                    int s = atomicAdd(&scnt[g], 1);
                    if (s < LCAP) slist[g * LCAP + s] = (short)i;
                }
            }
        } else {
            const long long* p = (const long long*)idx_raw;
            #pragma unroll 4
            for (int i = t; i < R0; i += 256) {
                int g = (int)p[i] - g0;
                if ((unsigned)g < GPB) {
                    int s = atomicAdd(&scnt[g], 1);
                    if (s < LCAP) slist[g * LCAP + s] = (short)i;
                }
            }
        }
        __syncthreads();

        // block-uniform prefix over 8 group counts (computed by every thread)
        int soff[GPB + 1];
        {
            int acc = 0;
            #pragma unroll
            for (int g = 0; g < GPB; g++) {
                soff[g] = acc;
                int cg = scnt[g];
                if (cg > LCAP) cg = LCAP;
                acc += cg;
                if (acc > FCAP) acc = FCAP;
            }
            soff[GPB] = acc;
        }
        // compact into flat ordered list
        #pragma unroll
        for (int g = 0; g < GPB; g++) {
            int cg = soff[g + 1] - soff[g];
            for (int s = t; s < cg; s += 256)
                sflat[soff[g] + s] = slist[g * LCAP + s];
        }
        __syncthreads();

        int total = soff[GPB];
        int gg = 0;
        int bnd = soff[1];
        float ax = 0.f, ay = 0.f, az = 0.f, aw = 0.f;   // current group sum
        float px = 0.f, py = 0.f, pz = 0.f, pw = 0.f;   // p2 partial (8 groups)
        float lsum = 0.f;                                // loss_a partial

#define FLUSH_GROUP() do {                                                   \
            float4 o_ = *(const float4*)(obs0 + (size_t)(g0 + gg) * C0 + c); \
            float dx_ = o_.x - ax, dy_ = o_.y - ay;                          \
            float dz_ = o_.z - az, dw_ = o_.w - aw;                          \
            lsum += dx_ * dx_ + dy_ * dy_ + dz_ * dz_ + dw_ * dw_;           \
            px += ax; py += ay; pz += az; pw += aw;                          \
            ax = ay = az = aw = 0.f;                                         \
        } while (0)

        for (int base = 0; base < total; base += 8) {
            float4 v[8];
            #pragma unroll
            for (int k = 0; k < 8; k++) {
                int idx = base + k;
                if (idx < total) {
                    int r = (unsigned short)sflat[idx];
                    v[k] = *(const float4*)(theta0 + (size_t)r * C0 + c);
                }
            }
            #pragma unroll
            for (int k = 0; k < 8; k++) {
                int idx = base + k;
                if (idx < total) {
                    while (idx == bnd) { FLUSH_GROUP(); gg++; bnd = soff[gg + 1]; }
                    ax += __expf(v[k].x); ay += __expf(v[k].y);
                    az += __expf(v[k].z); aw += __expf(v[k].w);
                }
            }
        }
        while (gg < GPB) { FLUSH_GROUP(); gg++; }
#undef FLUSH_GROUP

        atomicAdd(&g_p2[c + 0], px);
        atomicAdd(&g_p2[c + 1], py);
        atomicAdd(&g_p2[c + 2], pz);
        atomicAdd(&g_p2[c + 3], pw);

        float v = block_reduce256(lsum, sh);
        if (t == 0) atomicAdd(&g_loss[0], (double)v);
    } else {
        // ----------------- p1 rowsum-of-exp: one warp per theta1 row -------
        int gid = (bx >> 1) * 256 + threadIdx.x;
        int w = gid >> 5, lane = gid & 31;
        const float4* row = (const float4*)(theta1 + (size_t)w * C1);
        float s = 0.f;
        #pragma unroll 4
        for (int j = lane; j < C1 / 4; j += 32) {
            float4 v = row[j];
            s += __expf(v.x) + __expf(v.y) + __expf(v.z) + __expf(v.w);
        }
        #pragma unroll
        for (int o = 16; o; o >>= 1) s += __shfl_down_sync(0xffffffffu, s, o);
        if (lane == 0) g_p1[w] = s;
    }
}

// ---------------------------------------------------------------------------
// Epilogue (R6 configuration — best measured: 7.4 us; 528 blocks).
//  blocks [0, C_BLOCKS): obs-C + restore g_p2.
//  blocks [C_BLOCKS, +B_BLOCKS): obs-B — ONE BLOCK PER mapping1 ROW
//    (512 blocks; each thread owns 4 float4 of the 4096-dot; p1 is 16 KB,
//    L1/L2-resident). Last finisher writes the output and restores the
//    accumulators for the next graph replay.
// ---------------------------------------------------------------------------
__global__ __launch_bounds__(256) void k_post(const float* __restrict__ obs2,
                                              const float* __restrict__ mapping1,
                                              const float* __restrict__ obs1,
                                              float* __restrict__ out) {
    __shared__ float sh[8];
    int bx = blockIdx.x;
    int t = threadIdx.x;
    if (bx < C_BLOCKS) {
        int c = bx * 256 + t;
        float d = obs2[c] - g_p2[c];
        g_p2[c] = 0.f;                      // restore for next call
        float v = block_reduce256(d * d, sh);
        if (t == 0) atomicAdd(&g_loss[2], (double)v);
    } else {
        int w = bx - C_BLOCKS;              // output row 0..511
        const float4* row = (const float4*)(mapping1 + (size_t)w * C0);
        const float4* p = (const float4*)g_p1;
        float s = 0.f;
        #pragma unroll
        for (int j = 0; j < 4; j++) {       // 4 independent float4 pairs
            int k = t + j * 256;
            float4 m = row[k];
            float4 q = p[k];
            s += m.x * q.x + m.y * q.y + m.z * q.z + m.w * q.w;
        }
        float v = block_reduce256(s, sh);
        if (t == 0) {
            double d = (double)obs1[w] - (double)v;
            atomicAdd(&g_loss[1], d * d);
        }
    }
    __syncthreads();
    __threadfence();
    if (t == 0) {
        int done = atomicAdd(&g_done, 1);
        if (done == (int)gridDim.x - 1) {
            __threadfence();
            double la = *(volatile double*)&g_loss[0];
            double lb = *(volatile double*)&g_loss[1];
            double lc = *(volatile double*)&g_loss[2];
            la /= (double)((size_t)NG * (size_t)C0);
            lb /= (double)RM;
            lc = 0.5 * lc / (double)C0;
            out[0] = (float)((la + lb + lc) / 3.0);
            g_loss[0] = 0.0; g_loss[1] = 0.0; g_loss[2] = 0.0;
            g_done = 0;
        }
    }
}

extern "C" void kernel_launch(void* const* d_in, const int* in_sizes, int n_in,
                              void* d_out, int out_size) {
    const float* theta0   = (const float*)d_in[0];
    const float* theta1   = (const float*)d_in[1];
    const float* obs0     = (const float*)d_in[2];
    const float* obs1     = (const float*)d_in[3];
    const float* obs2     = (const float*)d_in[4];
    const void*  idx0     = d_in[5];
    const float* mapping1 = (const float*)d_in[6];
    float* out = (float*)d_out;

    k_main<<<A_BLOCKS + P1_BLOCKS, 256>>>(theta0, obs0, theta1,
                                          (const unsigned int*)idx0);
    k_post<<<C_BLOCKS + B_BLOCKS, 256>>>(obs2, mapping1, obs1, out);
}